// round 14
// baseline (speedup 1.0000x reference)
#include <cuda_runtime.h>
#include <cuda_fp16.h>
#include <cstddef>

#define D 64
#define NH 4
#define DH 16
#define FF 2048
#define VV 1000000
#define STEPS 10
#define EPS 1e-5f
#define PB 32
#define NTT 512
#define NBS 1184
#define NTS 256

// Dynamic smem layout (float offsets) for transformer weights.
#define W_IPW  0       // 24576 (both layers contiguous as in global)
#define W_OW   24576   // 8192
#define W_F1   32768   // 8192 (block slice, [l][u][c])
#define W_F2   40960   // 8192 (block slice, [l][d][c])
#define W_IPB  49152   // 384
#define W_OB   49536   // 128
#define W_F1B  49664   // 128 (slice)
#define W_F2B  49792   // 128
#define W_L1W  49920   // 128
#define W_L1B  50048   // 128
#define W_L2W  50176   // 128
#define W_L2B  50304   // 128
#define DYN_FLOATS 50432
#define DYN_BYTES (DYN_FLOATS * 4)

// Persistent device state (reset by init kernel each launch).
__device__ float g_y0s[STEPS * STEPS * D];
__device__ float g_x1b[D];
__device__ float g_y1part[PB * D];
__device__ float g_xf[D];
__device__ unsigned long long g_amax8[STEPS][8];
__device__ int g_gen[STEPS];
__device__ uint4 g_embT[8ull * VV];
__device__ int g_minis[STEPS];
__device__ int g_p2cs[STEPS];

__device__ __forceinline__ unsigned int fkey(float f) {
    unsigned int u = __float_as_uint(f);
    return (u & 0x80000000u) ? ~u : (u | 0x80000000u);
}
__device__ __forceinline__ int dec_idx(unsigned long long k) {
    return (int)(0xFFFFFFFFu - (unsigned int)(k & 0xFFFFFFFFull));
}
__device__ __forceinline__ float dot4(float4 a, float4 b) {
    return a.x * b.x + a.y * b.y + a.z * b.z + a.w * b.w;
}
__device__ __forceinline__ uint4 pack8(float4 a, float4 b) {
    uint4 o;
    __half2 h;
    h = __floats2half2_rn(a.x, a.y); o.x = *(unsigned int*)&h;
    h = __floats2half2_rn(a.z, a.w); o.y = *(unsigned int*)&h;
    h = __floats2half2_rn(b.x, b.y); o.z = *(unsigned int*)&h;
    h = __floats2half2_rn(b.z, b.w); o.w = *(unsigned int*)&h;
    return o;
}
__device__ __forceinline__ float dot8h(uint4 q, float4 xa, float4 xb) {
    __half2* hp = (__half2*)&q;
    float2 f0 = __half22float2(hp[0]), f1 = __half22float2(hp[1]);
    float2 f2 = __half22float2(hp[2]), f3 = __half22float2(hp[3]);
    return f0.x * xa.x + f0.y * xa.y + f1.x * xa.z + f1.y * xa.w
         + f2.x * xb.x + f2.y * xb.y + f3.x * xb.z + f3.y * xb.w;
}
__device__ __forceinline__ float red8(float v) {
    v += __shfl_xor_sync(0xffffffffu, v, 4);
    v += __shfl_xor_sync(0xffffffffu, v, 2);
    v += __shfl_xor_sync(0xffffffffu, v, 1);
    return v;
}

// ---------------------------------------------------------------------------
__global__ void init_kernel() {
    int tid = threadIdx.x;
    if (tid < STEPS * 8) ((unsigned long long*)g_amax8)[tid] = 0ull;
    if (tid < STEPS) { g_minis[tid] = 0; g_p2cs[tid] = 0; }
    for (int i = tid; i < STEPS * STEPS * D; i += 256) g_y0s[i] = 0.f;
}

// ---------------------------------------------------------------------------
// Fused transformer step with smem-pinned weights. 32 blocks x 512 threads.
// ---------------------------------------------------------------------------
__global__ void __launch_bounds__(NTT, 1)
transformer_kernel(const float* __restrict__ ht, const float* __restrict__ emb,
                   const float* __restrict__ pos, const float* __restrict__ ipw,
                   const float* __restrict__ ipb, const float* __restrict__ ow,
                   const float* __restrict__ ob, const float* __restrict__ ln1w,
                   const float* __restrict__ ln1b, const float* __restrict__ ln2w,
                   const float* __restrict__ ln2b, const float* __restrict__ f1w,
                   const float* __restrict__ f1b, const float* __restrict__ f2w,
                   const float* __restrict__ f2b, int t) {
    extern __shared__ float dsm[];
    float* wipw = dsm + W_IPW;
    float* wow  = dsm + W_OW;
    float* wf1  = dsm + W_F1;
    float* wf2  = dsm + W_F2;
    float* wipb = dsm + W_IPB;
    float* wob  = dsm + W_OB;
    float* wf1b = dsm + W_F1B;
    float* wf2b = dsm + W_F2B;
    float* wl1w = dsm + W_L1W;
    float* wl1b = dsm + W_L1B;
    float* wl2w = dsm + W_L2W;
    float* wl2b = dsm + W_L2B;

    __shared__ __align__(16) float sA[STEPS * D];
    __shared__ __align__(16) float sQ[STEPS * 3 * D];
    __shared__ __align__(16) float sO[STEPS * D];
    __shared__ float sSC[NH * STEPS * STEPS];
    __shared__ float sST[2 * STEPS + 4];
    __shared__ int sgen[STEPS];
    __shared__ int s_last;

    const int tid = threadIdx.x, blk = blockIdx.x;
    const int g8 = tid >> 3, r8 = tid & 7;
    const int S = t + 1;

    // ---- Weight prefetch into smem (one high-MLP burst; float4 granularity) ----
    {
        float4* d4;
        const float4* s4;
        d4 = (float4*)wipw; s4 = (const float4*)ipw;            // 24576 floats
        for (int i = tid; i < 6144; i += NTT) d4[i] = s4[i];
        d4 = (float4*)wow; s4 = (const float4*)ow;              // 8192 floats
        for (int i = tid; i < 2048; i += NTT) d4[i] = s4[i];
        // f1 slice: [l][u][c], 64 units * 64 c * 2 layers
        d4 = (float4*)wf1;
        for (int i = tid; i < 2048; i += NTT) {
            int l = i >> 10, u = (i >> 4) & 63, c4 = i & 15;
            d4[i] = ((const float4*)(f1w + (size_t)l * FF * D + (size_t)(blk * 64 + u) * D))[c4];
        }
        // f2 slice: [l][d][c]
        d4 = (float4*)wf2;
        for (int i = tid; i < 2048; i += NTT) {
            int l = i >> 10, d = (i >> 4) & 63, c4 = i & 15;
            d4[i] = ((const float4*)(f2w + (size_t)l * D * FF + (size_t)d * FF + blk * 64))[c4];
        }
        for (int i = tid; i < 384; i += NTT) wipb[i] = ipb[i];
        if (tid < 128) {
            wob[tid] = ob[tid];
            wf2b[tid] = f2b[tid];
            wl1w[tid] = ln1w[tid];
            wl1b[tid] = ln1b[tid];
            wl2w[tid] = ln2w[tid];
            wl2b[tid] = ln2b[tid];
            wf1b[tid] = f1b[(tid >> 6) * FF + blk * 64 + (tid & 63)];
        }
    }

    // ---- argmax decode / input stack (overlaps with weight loads in flight) ----
    if (tid < t) {
        int gi;
        if (tid == t - 1) {
            unsigned long long m = 0ull;
#pragma unroll
            for (int k2 = 0; k2 < 8; k2++) {
                unsigned long long a = g_amax8[t - 1][k2];
                if (a > m) m = a;
            }
            gi = dec_idx(m);
            if (blk == 0) g_gen[t - 1] = gi;
        } else {
            gi = g_gen[tid];
        }
        sgen[tid] = gi;
    }
    __syncthreads();
    for (int i = tid; i < S * D; i += NTT) {
        int s = i >> 6, d = i & 63;
        float base = (s == 0) ? ht[d] : emb[(size_t)sgen[s - 1] * D + d];
        sA[i] = base + pos[i];
    }
    __syncthreads();

    // -------- P1: layer-0 attention (redundant per block) --------
    for (int i = tid; i < S * 3 * D; i += NTT) {
        int s = i / 192, j = i % 192;
        const float4* wr = (const float4*)(wipw + j * D);
        const float4* xr = (const float4*)(sA + s * D);
        float acc = wipb[j];
#pragma unroll
        for (int k = 0; k < 16; k++) acc += dot4(wr[k], xr[k]);
        sQ[i] = acc;
    }
    __syncthreads();
    for (int i = tid; i < NH * S * S; i += NTT) {
        int h = i / (S * S), r = (i / S) % S, c = i % S;
        const float* q = sQ + r * 192 + h * DH;
        const float* k = sQ + c * 192 + D + h * DH;
        float acc = 0.f;
#pragma unroll
        for (int d = 0; d < DH; d++) acc += q[d] * k[d];
        sSC[(h * S + r) * S + c] = acc * 0.25f;
    }
    __syncthreads();
    if (tid < NH * S) {
        float* row = sSC + tid * S;
        float mx = row[0];
        for (int c = 1; c < S; c++) mx = fmaxf(mx, row[c]);
        float sm = 0.f;
        for (int c = 0; c < S; c++) { float e = expf(row[c] - mx); row[c] = e; sm += e; }
        float inv = 1.f / sm;
        for (int c = 0; c < S; c++) row[c] *= inv;
    }
    __syncthreads();
    for (int i = tid; i < S * D; i += NTT) {
        int s = i >> 6, col = i & 63, h = col >> 4, d = col & 15;
        const float* a = sSC + (h * S + s) * S;
        float acc = 0.f;
        for (int c = 0; c < S; c++) acc += a[c] * sQ[c * 192 + 2 * D + h * DH + d];
        sO[i] = acc;
    }
    __syncthreads();
    for (int i = tid; i < S * D; i += NTT) {
        int s = i >> 6, e = i & 63;
        const float4* wr = (const float4*)(wow + e * D);
        const float4* orow = (const float4*)(sO + s * D);
        float acc = wob[e];
#pragma unroll
        for (int k = 0; k < 16; k++) acc += dot4(wr[k], orow[k]);
        sQ[i] = sA[i] + acc;
    }
    __syncthreads();
    if (tid < S) {
        float m = 0.f;
        for (int d = 0; d < D; d++) m += sQ[tid * D + d];
        m *= (1.f / D);
        float vv = 0.f;
        for (int d = 0; d < D; d++) { float df = sQ[tid * D + d] - m; vv += df * df; }
        vv *= (1.f / D);
        sST[tid * 2] = m;
        sST[tid * 2 + 1] = rsqrtf(vv + EPS);
    }
    __syncthreads();
    for (int i = tid; i < S * D; i += NTT) {
        int s = i >> 6, d = i & 63;
        sA[i] = (sQ[i] - sST[s * 2]) * sST[s * 2 + 1] * wl1w[d] + wl1b[d];
    }
    __syncthreads();
    {   // ffn0: 64 units per block (weights from smem)
        const float4* w1r = (const float4*)(wf1 + g8 * 64);
        float4 wa = w1r[2 * r8], wb = w1r[2 * r8 + 1];
        float b1 = wf1b[g8];
        const float4* x4 = (const float4*)sA;
        for (int s = 0; s < S; s++) {
            float v = red8(dot4(wa, x4[s * 16 + 2 * r8]) + dot4(wb, x4[s * 16 + 2 * r8 + 1]));
            if (r8 == 0) sO[s * 64 + g8] = fmaxf(v + b1, 0.f);
        }
        __syncthreads();
        const float4* w2r = (const float4*)(wf2 + g8 * 64);
        float4 va = w2r[2 * r8], vb = w2r[2 * r8 + 1];
        const float4* h4 = (const float4*)sO;
        for (int s = 0; s < S; s++) {
            float r = red8(dot4(va, h4[s * 16 + 2 * r8]) + dot4(vb, h4[s * 16 + 2 * r8 + 1]));
            if (r8 == 0) atomicAdd(&g_y0s[t * (STEPS * D) + s * 64 + g8], r);
        }
    }
    // -------- mini barrier among 32 blocks --------
    __threadfence();
    __syncthreads();
    if (tid == 0) {
        atomicAdd(&g_minis[t], 1);
        while (*(volatile int*)&g_minis[t] < PB) __nanosleep(32);
    }
    __syncthreads();
    __threadfence();

    // -------- P2: layer-1 attn last-row (redundant) + ffn1 slice --------
    for (int i = tid; i < S * D; i += NTT)
        sA[i] = sA[i] + __ldcg(&g_y0s[t * (STEPS * D) + i]) + wf2b[i & 63];
    __syncthreads();
    if (tid < S) {
        float m = 0.f;
        for (int d = 0; d < D; d++) m += sA[tid * D + d];
        m *= (1.f / D);
        float vv = 0.f;
        for (int d = 0; d < D; d++) { float df = sA[tid * D + d] - m; vv += df * df; }
        vv *= (1.f / D);
        sST[tid * 2] = m;
        sST[tid * 2 + 1] = rsqrtf(vv + EPS);
    }
    __syncthreads();
    for (int i = tid; i < S * D; i += NTT) {
        int s = i >> 6, d = i & 63;
        sA[i] = (sA[i] - sST[s * 2]) * sST[s * 2 + 1] * wl2w[d] + wl2b[d];
    }
    __syncthreads();
    for (int i = tid; i < S * 3 * D; i += NTT) {
        int s = i / 192, j = i % 192;
        const float4* wr = (const float4*)(wipw + (192 + j) * D);
        const float4* xr = (const float4*)(sA + s * D);
        float acc = wipb[192 + j];
#pragma unroll
        for (int k = 0; k < 16; k++) acc += dot4(wr[k], xr[k]);
        sQ[i] = acc;
    }
    __syncthreads();
    if (tid < NH * S) {
        int h = tid / S, c = tid % S;
        const float* q = sQ + (S - 1) * 192 + h * DH;
        const float* k = sQ + c * 192 + D + h * DH;
        float acc = 0.f;
#pragma unroll
        for (int d = 0; d < DH; d++) acc += q[d] * k[d];
        sSC[h * S + c] = acc * 0.25f;
    }
    __syncthreads();
    if (tid < NH) {
        float* row = sSC + tid * S;
        float mx = row[0];
        for (int c = 1; c < S; c++) mx = fmaxf(mx, row[c]);
        float sm = 0.f;
        for (int c = 0; c < S; c++) { float e = expf(row[c] - mx); row[c] = e; sm += e; }
        float inv = 1.f / sm;
        for (int c = 0; c < S; c++) row[c] *= inv;
    }
    __syncthreads();
    if (tid < D) {
        int h = tid >> 4, d = tid & 15;
        const float* a = sSC + h * S;
        float acc = 0.f;
        for (int c = 0; c < S; c++) acc += a[c] * sQ[c * 192 + 2 * D + h * DH + d];
        sO[tid] = acc;
    }
    __syncthreads();
    if (tid < D) {
        const float4* wr = (const float4*)(wow + (D + tid) * D);
        const float4* orow = (const float4*)sO;
        float acc = wob[D + tid];
#pragma unroll
        for (int k = 0; k < 16; k++) acc += dot4(wr[k], orow[k]);
        sQ[tid] = sA[(S - 1) * D + tid] + acc;
    }
    __syncthreads();
    if (tid == 0) {
        float m = 0.f;
        for (int d = 0; d < D; d++) m += sQ[d];
        m *= (1.f / D);
        float vv = 0.f;
        for (int d = 0; d < D; d++) { float df = sQ[d] - m; vv += df * df; }
        vv *= (1.f / D);
        sST[20] = m;
        sST[21] = rsqrtf(vv + EPS);
    }
    __syncthreads();
    if (tid < D) {
        float xl = (sQ[tid] - sST[20]) * sST[21] * wl1w[D + tid] + wl1b[D + tid];
        sA[tid] = xl;
        if (blk == 0) __stcg(&g_x1b[tid], xl);
    }
    __syncthreads();
    {   // ffn1 last row -> per-block partial (weights from smem)
        const float4* w1r = (const float4*)(wf1 + 4096 + g8 * 64);
        float4 wa = w1r[2 * r8], wb = w1r[2 * r8 + 1];
        const float4* x4 = (const float4*)sA;
        float v = red8(dot4(wa, x4[2 * r8]) + dot4(wb, x4[2 * r8 + 1]));
        if (r8 == 0) sO[g8] = fmaxf(v + wf1b[64 + g8], 0.f);
        __syncthreads();
        const float4* w2r = (const float4*)(wf2 + 4096 + g8 * 64);
        float4 va = w2r[2 * r8], vb = w2r[2 * r8 + 1];
        const float4* h4 = (const float4*)sO;
        float r = red8(dot4(va, h4[2 * r8]) + dot4(vb, h4[2 * r8 + 1]));
        if (r8 == 0) __stcg(&g_y1part[blk * 64 + g8], r);
    }
    __threadfence();
    __syncthreads();
    if (tid == 0) s_last = atomicAdd(&g_p2cs[t], 1);
    __syncthreads();
    if (s_last == PB - 1) {
        if (tid < D) {
            float v = __ldcg(&g_x1b[tid]) + wf2b[64 + tid];
#pragma unroll
            for (int b = 0; b < PB; b++) v += __ldcg(&g_y1part[b * 64 + tid]);
            sQ[tid] = v;
        }
        __syncthreads();
        if (tid == 0) {
            float m = 0.f;
            for (int d = 0; d < D; d++) m += sQ[d];
            m *= (1.f / D);
            float vv = 0.f;
            for (int d = 0; d < D; d++) { float df = sQ[d] - m; vv += df * df; }
            vv *= (1.f / D);
            sST[0] = m;
            sST[1] = rsqrtf(vv + EPS);
        }
        __syncthreads();
        if (tid < D)
            g_xf[tid] = (sQ[tid] - sST[0]) * sST[1] * wl2w[64 + tid] + wl2b[64 + tid];
    }
}

// ---------------------------------------------------------------------------
__global__ void scan0_kernel(const float* __restrict__ emb,
                             float* __restrict__ out) {
    __shared__ __align__(16) float xs[D];
    __shared__ unsigned long long sbs[NTS];
    const int tid = threadIdx.x, blk = blockIdx.x;
    const int lane = tid & 31, wrp = tid >> 5;
    const int grp = lane >> 3, l8 = lane & 7;
    if (tid < D) xs[tid] = g_xf[tid];
    __syncthreads();
    const float4* xs4 = (const float4*)xs;
    float4 xa = xs4[2 * l8], xb = xs4[2 * l8 + 1];
    unsigned long long best = 0ull;

    for (int u = blk * 8 + wrp; u < 62500; u += NBS * 8) {
        int v0 = u * 16 + grp * 4;
        float4 av[4], bv[4];
#pragma unroll
        for (int r = 0; r < 4; r++) {
            const float4* p = (const float4*)(emb + (size_t)(v0 + r) * D);
            av[r] = __ldcg(p + 2 * l8);
            bv[r] = __ldcg(p + 2 * l8 + 1);
        }
        float keep = 0.f;
#pragma unroll
        for (int r = 0; r < 4; r++) {
            __stcg(&g_embT[(size_t)l8 * VV + v0 + r], pack8(av[r], bv[r]));
            float dot = dot4(av[r], xa) + dot4(bv[r], xb);
            dot += __shfl_xor_sync(0xffffffffu, dot, 1);
            dot += __shfl_xor_sync(0xffffffffu, dot, 2);
            dot += __shfl_xor_sync(0xffffffffu, dot, 4);
            if (l8 == r) keep = dot;
        }
        if (l8 < 4) {
            int v = v0 + l8;
            __stcg(&out[v], keep);
            unsigned long long key =
                ((unsigned long long)fkey(keep) << 32) | (0xFFFFFFFFu - (unsigned)v);
            if (key > best) best = key;
        }
    }

    sbs[tid] = best;
    __syncthreads();
    for (int o2 = NTS / 2; o2; o2 >>= 1) {
        if (tid < o2) { if (sbs[tid + o2] > sbs[tid]) sbs[tid] = sbs[tid + o2]; }
        __syncthreads();
    }
    if (tid == 0) atomicMax(&g_amax8[0][blk & 7], sbs[0]);
}

// ---------------------------------------------------------------------------
__global__ void scan_kernel(float* __restrict__ out, int t) {
    __shared__ __align__(16) float xs[D];
    __shared__ unsigned long long sbs[NTS];
    const int tid = threadIdx.x, blk = blockIdx.x;
    if (tid < D) xs[tid] = g_xf[tid];
    __syncthreads();
    const float4* xs4 = (const float4*)xs;
    unsigned long long best = 0ull;
    float* orow = out + (size_t)t * VV;

#pragma unroll
    for (int i = 0; i < 4; i++) {
        int v = i * (NBS * NTS) + blk * NTS + tid;
        if (v >= VV) break;
        uint4 q[8];
#pragma unroll
        for (int j = 0; j < 8; j++)
            q[j] = __ldcg(&g_embT[(size_t)j * VV + v]);
        float dot = 0.f;
#pragma unroll
        for (int j = 0; j < 8; j++)
            dot += dot8h(q[j], xs4[2 * j], xs4[2 * j + 1]);
        __stcg(&orow[v], dot);
        unsigned long long key =
            ((unsigned long long)fkey(dot) << 32) | (0xFFFFFFFFu - (unsigned)v);
        if (key > best) best = key;
    }

    sbs[tid] = best;
    __syncthreads();
    for (int o2 = NTS / 2; o2; o2 >>= 1) {
        if (tid < o2) { if (sbs[tid + o2] > sbs[tid]) sbs[tid] = sbs[tid + o2]; }
        __syncthreads();
    }
    if (tid == 0) atomicMax(&g_amax8[t][blk & 7], sbs[0]);
}

// ---------------------------------------------------------------------------
__global__ void fin_kernel(float* out, int out_size) {
    if (threadIdx.x == 0) {
        unsigned long long m = 0ull;
#pragma unroll
        for (int k2 = 0; k2 < 8; k2++) {
            unsigned long long a = g_amax8[STEPS - 1][k2];
            if (a > m) m = a;
        }
        g_gen[STEPS - 1] = dec_idx(m);
    }
    __syncthreads();
    if (out_size >= STEPS * VV + STEPS && threadIdx.x < STEPS)
        out[(size_t)STEPS * VV + threadIdx.x] = (float)g_gen[threadIdx.x];
}

extern "C" void kernel_launch(void* const* d_in, const int* in_sizes, int n_in,
                              void* d_out, int out_size) {
    const float* ht  = (const float*)d_in[0];
    const float* emb = (const float*)d_in[1];
    const float* pos = (const float*)d_in[2];
    const float* ipw = (const float*)d_in[3];
    const float* ipb = (const float*)d_in[4];
    const float* ow  = (const float*)d_in[5];
    const float* ob  = (const float*)d_in[6];
    const float* l1w = (const float*)d_in[7];
    const float* l1b = (const float*)d_in[8];
    const float* l2w = (const float*)d_in[9];
    const float* l2b = (const float*)d_in[10];
    const float* f1w = (const float*)d_in[11];
    const float* f1b = (const float*)d_in[12];
    const float* f2w = (const float*)d_in[13];
    const float* f2b = (const float*)d_in[14];
    float* out = (float*)d_out;

    cudaFuncSetAttribute(transformer_kernel,
                         cudaFuncAttributeMaxDynamicSharedMemorySize, DYN_BYTES);
    init_kernel<<<1, 256>>>();
    for (int t = 0; t < STEPS; t++) {
        transformer_kernel<<<PB, NTT, DYN_BYTES>>>(ht, emb, pos, ipw, ipb, ow,
                                                   ob, l1w, l1b, l2w, l2b,
                                                   f1w, f1b, f2w, f2b, t);
        if (t == 0) scan0_kernel<<<NBS, NTS>>>(emb, out);
        else scan_kernel<<<NBS, NTS>>>(out, t);
    }
    fin_kernel<<<1, 32>>>(out, out_size);
}

// round 15
// speedup vs baseline: 1.1967x; 1.1967x over previous
#include <cuda_runtime.h>
#include <cuda_fp16.h>
#include <cstddef>

#define D 64
#define NH 4
#define DH 16
#define FF 2048
#define VV 1000000
#define STEPS 10
#define EPS 1e-5f
#define PB 32       // transformer blocks
#define NTT 512     // transformer threads
#define NBS 1184    // scan blocks (8/SM at 256 thr)
#define NTS 256     // scan threads

// Persistent device state (reset by init kernel each launch).
__device__ float g_y0s[STEPS * STEPS * D];
__device__ float g_x1b[D];
__device__ float g_y1part[PB * D];
__device__ float g_xf[D];
__device__ unsigned long long g_amax8[STEPS][8];
__device__ int g_gen[STEPS];
__device__ uint4 g_embT[8ull * VV];  // chunk-major fp16 emb (written by scan0)
__device__ int g_minis[STEPS];
__device__ int g_p2cs[STEPS];

__device__ __forceinline__ unsigned int fkey(float f) {
    unsigned int u = __float_as_uint(f);
    return (u & 0x80000000u) ? ~u : (u | 0x80000000u);
}
__device__ __forceinline__ int dec_idx(unsigned long long k) {
    return (int)(0xFFFFFFFFu - (unsigned int)(k & 0xFFFFFFFFull));
}
__device__ __forceinline__ float dot4(float4 a, float4 b) {
    return a.x * b.x + a.y * b.y + a.z * b.z + a.w * b.w;
}
__device__ __forceinline__ uint4 pack8(float4 a, float4 b) {
    uint4 o;
    __half2 h;
    h = __floats2half2_rn(a.x, a.y); o.x = *(unsigned int*)&h;
    h = __floats2half2_rn(a.z, a.w); o.y = *(unsigned int*)&h;
    h = __floats2half2_rn(b.x, b.y); o.z = *(unsigned int*)&h;
    h = __floats2half2_rn(b.z, b.w); o.w = *(unsigned int*)&h;
    return o;
}
__device__ __forceinline__ float dot8h(uint4 q, float4 xa, float4 xb) {
    __half2* hp = (__half2*)&q;
    float2 f0 = __half22float2(hp[0]), f1 = __half22float2(hp[1]);
    float2 f2 = __half22float2(hp[2]), f3 = __half22float2(hp[3]);
    return f0.x * xa.x + f0.y * xa.y + f1.x * xa.z + f1.y * xa.w
         + f2.x * xb.x + f2.y * xb.y + f3.x * xb.z + f3.y * xb.w;
}
__device__ __forceinline__ float red8(float v) {
    v += __shfl_xor_sync(0xffffffffu, v, 4);
    v += __shfl_xor_sync(0xffffffffu, v, 2);
    v += __shfl_xor_sync(0xffffffffu, v, 1);
    return v;
}

// ---------------------------------------------------------------------------
__global__ void init_kernel() {
    int tid = threadIdx.x;
    if (tid < STEPS * 8) ((unsigned long long*)g_amax8)[tid] = 0ull;
    if (tid < STEPS) { g_minis[tid] = 0; g_p2cs[tid] = 0; }
    for (int i = tid; i < STEPS * STEPS * D; i += 256) g_y0s[i] = 0.f;
}

// ---------------------------------------------------------------------------
// Fused transformer step (R13 form — weights via normal caching loads, which
// now stay L2-resident because the scans use streaming/evict-first hints).
// ---------------------------------------------------------------------------
__global__ void __launch_bounds__(NTT, 1)
transformer_kernel(const float* __restrict__ ht, const float* __restrict__ emb,
                   const float* __restrict__ pos, const float* __restrict__ ipw,
                   const float* __restrict__ ipb, const float* __restrict__ ow,
                   const float* __restrict__ ob, const float* __restrict__ ln1w,
                   const float* __restrict__ ln1b, const float* __restrict__ ln2w,
                   const float* __restrict__ ln2b, const float* __restrict__ f1w,
                   const float* __restrict__ f1b, const float* __restrict__ f2w,
                   const float* __restrict__ f2b, int t) {
    __shared__ __align__(16) float sA[STEPS * D];
    __shared__ __align__(16) float sQ[STEPS * 3 * D];
    __shared__ __align__(16) float sO[STEPS * D];
    __shared__ float sSC[NH * STEPS * STEPS];
    __shared__ float sST[2 * STEPS + 4];
    __shared__ int sgen[STEPS];
    __shared__ int s_last;

    const int tid = threadIdx.x, blk = blockIdx.x;
    const int g8 = tid >> 3, r8 = tid & 7;
    const int S = t + 1;

    // -------- P1: layer-0 attention (redundant per block) --------
    if (tid < t) {
        int gi;
        if (tid == t - 1) {
            unsigned long long m = 0ull;
#pragma unroll
            for (int k2 = 0; k2 < 8; k2++) {
                unsigned long long a = g_amax8[t - 1][k2];
                if (a > m) m = a;
            }
            gi = dec_idx(m);
            if (blk == 0) g_gen[t - 1] = gi;
        } else {
            gi = g_gen[tid];
        }
        sgen[tid] = gi;
    }
    __syncthreads();
    for (int i = tid; i < S * D; i += NTT) {
        int s = i >> 6, d = i & 63;
        float base = (s == 0) ? ht[d] : emb[(size_t)sgen[s - 1] * D + d];
        sA[i] = base + pos[i];
    }
    __syncthreads();
    for (int i = tid; i < S * 3 * D; i += NTT) {
        int s = i / 192, j = i % 192;
        const float4* wr = (const float4*)(ipw + (size_t)j * D);
        const float4* xr = (const float4*)(sA + s * D);
        float acc = ipb[j];
#pragma unroll
        for (int k = 0; k < 16; k++) acc += dot4(wr[k], xr[k]);
        sQ[i] = acc;
    }
    __syncthreads();
    for (int i = tid; i < NH * S * S; i += NTT) {
        int h = i / (S * S), r = (i / S) % S, c = i % S;
        const float* q = sQ + r * 192 + h * DH;
        const float* k = sQ + c * 192 + D + h * DH;
        float acc = 0.f;
#pragma unroll
        for (int d = 0; d < DH; d++) acc += q[d] * k[d];
        sSC[(h * S + r) * S + c] = acc * 0.25f;
    }
    __syncthreads();
    if (tid < NH * S) {
        float* row = sSC + tid * S;
        float mx = row[0];
        for (int c = 1; c < S; c++) mx = fmaxf(mx, row[c]);
        float sm = 0.f;
        for (int c = 0; c < S; c++) { float e = expf(row[c] - mx); row[c] = e; sm += e; }
        float inv = 1.f / sm;
        for (int c = 0; c < S; c++) row[c] *= inv;
    }
    __syncthreads();
    for (int i = tid; i < S * D; i += NTT) {
        int s = i >> 6, col = i & 63, h = col >> 4, d = col & 15;
        const float* a = sSC + (h * S + s) * S;
        float acc = 0.f;
        for (int c = 0; c < S; c++) acc += a[c] * sQ[c * 192 + 2 * D + h * DH + d];
        sO[i] = acc;
    }
    __syncthreads();
    for (int i = tid; i < S * D; i += NTT) {
        int s = i >> 6, e = i & 63;
        const float4* wr = (const float4*)(ow + (size_t)e * D);
        const float4* orow = (const float4*)(sO + s * D);
        float acc = ob[e];
#pragma unroll
        for (int k = 0; k < 16; k++) acc += dot4(wr[k], orow[k]);
        sQ[i] = sA[i] + acc;
    }
    __syncthreads();
    if (tid < S) {
        float m = 0.f;
        for (int d = 0; d < D; d++) m += sQ[tid * D + d];
        m *= (1.f / D);
        float vv = 0.f;
        for (int d = 0; d < D; d++) { float df = sQ[tid * D + d] - m; vv += df * df; }
        vv *= (1.f / D);
        sST[tid * 2] = m;
        sST[tid * 2 + 1] = rsqrtf(vv + EPS);
    }
    __syncthreads();
    for (int i = tid; i < S * D; i += NTT) {
        int s = i >> 6, d = i & 63;
        sA[i] = (sQ[i] - sST[s * 2]) * sST[s * 2 + 1] * ln1w[d] + ln1b[d];
    }
    __syncthreads();
    {   // ffn0: 64 units per block
        int f = blk * 64 + g8;
        const float4* w1r = (const float4*)(f1w + (size_t)f * D);
        float4 wa = w1r[2 * r8], wb = w1r[2 * r8 + 1];
        float b1 = f1b[f];
        const float4* x4 = (const float4*)sA;
        for (int s = 0; s < S; s++) {
            float v = red8(dot4(wa, x4[s * 16 + 2 * r8]) + dot4(wb, x4[s * 16 + 2 * r8 + 1]));
            if (r8 == 0) sO[s * 64 + g8] = fmaxf(v + b1, 0.f);
        }
        __syncthreads();
        const float4* w2r = (const float4*)(f2w + (size_t)g8 * FF + blk * 64);
        float4 va = w2r[2 * r8], vb = w2r[2 * r8 + 1];
        const float4* h4 = (const float4*)sO;
        for (int s = 0; s < S; s++) {
            float r = red8(dot4(va, h4[s * 16 + 2 * r8]) + dot4(vb, h4[s * 16 + 2 * r8 + 1]));
            if (r8 == 0) atomicAdd(&g_y0s[t * (STEPS * D) + s * 64 + g8], r);
        }
    }
    // -------- mini barrier among 32 blocks --------
    __threadfence();
    __syncthreads();
    if (tid == 0) {
        atomicAdd(&g_minis[t], 1);
        while (*(volatile int*)&g_minis[t] < PB) __nanosleep(32);
    }
    __syncthreads();
    __threadfence();

    // -------- P2: layer-1 attn last-row (redundant) + ffn1 slice --------
    for (int i = tid; i < S * D; i += NTT)
        sA[i] = sA[i] + __ldcg(&g_y0s[t * (STEPS * D) + i]) + f2b[i & 63];
    __syncthreads();
    if (tid < S) {
        float m = 0.f;
        for (int d = 0; d < D; d++) m += sA[tid * D + d];
        m *= (1.f / D);
        float vv = 0.f;
        for (int d = 0; d < D; d++) { float df = sA[tid * D + d] - m; vv += df * df; }
        vv *= (1.f / D);
        sST[tid * 2] = m;
        sST[tid * 2 + 1] = rsqrtf(vv + EPS);
    }
    __syncthreads();
    for (int i = tid; i < S * D; i += NTT) {
        int s = i >> 6, d = i & 63;
        sA[i] = (sA[i] - sST[s * 2]) * sST[s * 2 + 1] * ln2w[d] + ln2b[d];
    }
    __syncthreads();
    for (int i = tid; i < S * 3 * D; i += NTT) {
        int s = i / 192, j = i % 192;
        const float4* wr = (const float4*)(ipw + (size_t)(192 + j) * D);
        const float4* xr = (const float4*)(sA + s * D);
        float acc = ipb[192 + j];
#pragma unroll
        for (int k = 0; k < 16; k++) acc += dot4(wr[k], xr[k]);
        sQ[i] = acc;
    }
    __syncthreads();
    if (tid < NH * S) {
        int h = tid / S, c = tid % S;
        const float* q = sQ + (S - 1) * 192 + h * DH;
        const float* k = sQ + c * 192 + D + h * DH;
        float acc = 0.f;
#pragma unroll
        for (int d = 0; d < DH; d++) acc += q[d] * k[d];
        sSC[h * S + c] = acc * 0.25f;
    }
    __syncthreads();
    if (tid < NH) {
        float* row = sSC + tid * S;
        float mx = row[0];
        for (int c = 1; c < S; c++) mx = fmaxf(mx, row[c]);
        float sm = 0.f;
        for (int c = 0; c < S; c++) { float e = expf(row[c] - mx); row[c] = e; sm += e; }
        float inv = 1.f / sm;
        for (int c = 0; c < S; c++) row[c] *= inv;
    }
    __syncthreads();
    if (tid < D) {
        int h = tid >> 4, d = tid & 15;
        const float* a = sSC + h * S;
        float acc = 0.f;
        for (int c = 0; c < S; c++) acc += a[c] * sQ[c * 192 + 2 * D + h * DH + d];
        sO[tid] = acc;
    }
    __syncthreads();
    if (tid < D) {
        const float4* wr = (const float4*)(ow + (size_t)(D + tid) * D);
        const float4* orow = (const float4*)sO;
        float acc = ob[D + tid];
#pragma unroll
        for (int k = 0; k < 16; k++) acc += dot4(wr[k], orow[k]);
        sQ[tid] = sA[(S - 1) * D + tid] + acc;
    }
    __syncthreads();
    if (tid == 0) {
        float m = 0.f;
        for (int d = 0; d < D; d++) m += sQ[d];
        m *= (1.f / D);
        float vv = 0.f;
        for (int d = 0; d < D; d++) { float df = sQ[d] - m; vv += df * df; }
        vv *= (1.f / D);
        sST[20] = m;
        sST[21] = rsqrtf(vv + EPS);
    }
    __syncthreads();
    if (tid < D) {
        float xl = (sQ[tid] - sST[20]) * sST[21] * ln1w[D + tid] + ln1b[D + tid];
        sA[tid] = xl;
        if (blk == 0) __stcg(&g_x1b[tid], xl);
    }
    __syncthreads();
    {   // ffn1 last row -> per-block partial
        int f = blk * 64 + g8;
        const float4* w1r = (const float4*)(f1w + (size_t)FF * D + (size_t)f * D);
        float4 wa = w1r[2 * r8], wb = w1r[2 * r8 + 1];
        const float4* x4 = (const float4*)sA;
        float v = red8(dot4(wa, x4[2 * r8]) + dot4(wb, x4[2 * r8 + 1]));
        if (r8 == 0) sO[g8] = fmaxf(v + f1b[FF + f], 0.f);
        __syncthreads();
        const float4* w2r = (const float4*)(f2w + (size_t)D * FF + (size_t)g8 * FF + blk * 64);
        float4 va = w2r[2 * r8], vb = w2r[2 * r8 + 1];
        const float4* h4 = (const float4*)sO;
        float r = red8(dot4(va, h4[2 * r8]) + dot4(vb, h4[2 * r8 + 1]));
        if (r8 == 0) __stcg(&g_y1part[blk * 64 + g8], r);
    }
    __threadfence();
    __syncthreads();
    if (tid == 0) s_last = atomicAdd(&g_p2cs[t], 1);
    __syncthreads();
    if (s_last == PB - 1) {
        if (tid < D) {
            float v = __ldcg(&g_x1b[tid]) + f2b[D + tid];
#pragma unroll
            for (int b = 0; b < PB; b++) v += __ldcg(&g_y1part[b * 64 + tid]);
            sQ[tid] = v;
        }
        __syncthreads();
        if (tid == 0) {
            float m = 0.f;
            for (int d = 0; d < D; d++) m += sQ[d];
            m *= (1.f / D);
            float vv = 0.f;
            for (int d = 0; d < D; d++) { float df = sQ[d] - m; vv += df * df; }
            vv *= (1.f / D);
            sST[0] = m;
            sST[1] = rsqrtf(vv + EPS);
        }
        __syncthreads();
        if (tid < D)
            g_xf[tid] = (sQ[tid] - sST[0]) * sST[1] * ln2w[D + tid] + ln2b[D + tid];
    }
}

// ---------------------------------------------------------------------------
// Step-0 scan: STREAMING (evict-first) loads/stores so the 384 MB stream
// does not evict the transformer weight set from L2.
// ---------------------------------------------------------------------------
__global__ void scan0_kernel(const float* __restrict__ emb,
                             float* __restrict__ out) {
    __shared__ __align__(16) float xs[D];
    __shared__ unsigned long long sbs[NTS];
    const int tid = threadIdx.x, blk = blockIdx.x;
    const int lane = tid & 31, wrp = tid >> 5;
    const int grp = lane >> 3, l8 = lane & 7;
    if (tid < D) xs[tid] = g_xf[tid];
    __syncthreads();
    const float4* xs4 = (const float4*)xs;
    float4 xa = xs4[2 * l8], xb = xs4[2 * l8 + 1];
    unsigned long long best = 0ull;

    for (int u = blk * 8 + wrp; u < 62500; u += NBS * 8) {
        int v0 = u * 16 + grp * 4;
        float4 av[4], bv[4];
#pragma unroll
        for (int r = 0; r < 4; r++) {
            const float4* p = (const float4*)(emb + (size_t)(v0 + r) * D);
            av[r] = __ldcs(p + 2 * l8);
            bv[r] = __ldcs(p + 2 * l8 + 1);
        }
        float keep = 0.f;
#pragma unroll
        for (int r = 0; r < 4; r++) {
            __stcs(&g_embT[(size_t)l8 * VV + v0 + r], pack8(av[r], bv[r]));
            float dot = dot4(av[r], xa) + dot4(bv[r], xb);
            dot += __shfl_xor_sync(0xffffffffu, dot, 1);
            dot += __shfl_xor_sync(0xffffffffu, dot, 2);
            dot += __shfl_xor_sync(0xffffffffu, dot, 4);
            if (l8 == r) keep = dot;
        }
        if (l8 < 4) {
            int v = v0 + l8;
            __stcs(&out[v], keep);
            unsigned long long key =
                ((unsigned long long)fkey(keep) << 32) | (0xFFFFFFFFu - (unsigned)v);
            if (key > best) best = key;
        }
    }

    sbs[tid] = best;
    __syncthreads();
    for (int o2 = NTS / 2; o2; o2 >>= 1) {
        if (tid < o2) { if (sbs[tid + o2] > sbs[tid]) sbs[tid] = sbs[tid + o2]; }
        __syncthreads();
    }
    if (tid == 0) atomicMax(&g_amax8[0][blk & 7], sbs[0]);
}

// ---------------------------------------------------------------------------
// Steps 1-9 scan: STREAMING loads/stores (evict-first in L2).
// ---------------------------------------------------------------------------
__global__ void scan_kernel(float* __restrict__ out, int t) {
    __shared__ __align__(16) float xs[D];
    __shared__ unsigned long long sbs[NTS];
    const int tid = threadIdx.x, blk = blockIdx.x;
    if (tid < D) xs[tid] = g_xf[tid];
    __syncthreads();
    const float4* xs4 = (const float4*)xs;
    unsigned long long best = 0ull;
    float* orow = out + (size_t)t * VV;

#pragma unroll
    for (int i = 0; i < 4; i++) {
        int v = i * (NBS * NTS) + blk * NTS + tid;
        if (v >= VV) break;
        uint4 q[8];
#pragma unroll
        for (int j = 0; j < 8; j++)
            q[j] = __ldcs(&g_embT[(size_t)j * VV + v]);
        float dot = 0.f;
#pragma unroll
        for (int j = 0; j < 8; j++)
            dot += dot8h(q[j], xs4[2 * j], xs4[2 * j + 1]);
        __stcs(&orow[v], dot);
        unsigned long long key =
            ((unsigned long long)fkey(dot) << 32) | (0xFFFFFFFFu - (unsigned)v);
        if (key > best) best = key;
    }

    sbs[tid] = best;
    __syncthreads();
    for (int o2 = NTS / 2; o2; o2 >>= 1) {
        if (tid < o2) { if (sbs[tid + o2] > sbs[tid]) sbs[tid] = sbs[tid + o2]; }
        __syncthreads();
    }
    if (tid == 0) atomicMax(&g_amax8[t][blk & 7], sbs[0]);
}

// ---------------------------------------------------------------------------
__global__ void fin_kernel(float* out, int out_size) {
    if (threadIdx.x == 0) {
        unsigned long long m = 0ull;
#pragma unroll
        for (int k2 = 0; k2 < 8; k2++) {
            unsigned long long a = g_amax8[STEPS - 1][k2];
            if (a > m) m = a;
        }
        g_gen[STEPS - 1] = dec_idx(m);
    }
    __syncthreads();
    if (out_size >= STEPS * VV + STEPS && threadIdx.x < STEPS)
        out[(size_t)STEPS * VV + threadIdx.x] = (float)g_gen[threadIdx.x];
}

extern "C" void kernel_launch(void* const* d_in, const int* in_sizes, int n_in,
                              void* d_out, int out_size) {
    const float* ht  = (const float*)d_in[0];
    const float* emb = (const float*)d_in[1];
    const float* pos = (const float*)d_in[2];
    const float* ipw = (const float*)d_in[3];
    const float* ipb = (const float*)d_in[4];
    const float* ow  = (const float*)d_in[5];
    const float* ob  = (const float*)d_in[6];
    const float* l1w = (const float*)d_in[7];
    const float* l1b = (const float*)d_in[8];
    const float* l2w = (const float*)d_in[9];
    const float* l2b = (const float*)d_in[10];
    const float* f1w = (const float*)d_in[11];
    const float* f1b = (const float*)d_in[12];
    const float* f2w = (const float*)d_in[13];
    const float* f2b = (const float*)d_in[14];
    float* out = (float*)d_out;

    init_kernel<<<1, 256>>>();
    for (int t = 0; t < STEPS; t++) {
        transformer_kernel<<<PB, NTT>>>(ht, emb, pos, ipw, ipb, ow, ob,
                                        l1w, l1b, l2w, l2b, f1w, f1b,
                                        f2w, f2b, t);
        if (t == 0) scan0_kernel<<<NBS, NTS>>>(emb, out);
        else scan_kernel<<<NBS, NTS>>>(out, t);
    }
    fin_kernel<<<1, 32>>>(out, out_size);
}